// round 3
// baseline (speedup 1.0000x reference)
#include <cuda_runtime.h>
#include <math.h>

// Problem shape (fixed by setup_inputs)
constexpr int Bc = 8;     // batch
constexpr int Nc = 2048;  // nodes
constexpr int Fc = 128;   // in features
constexpr int Oc = 128;   // out features

// Scratch (static __device__ — allocation-free per harness rules)
__device__ float g_d[Bc * Nc];            // 64 KB: 1/(eps+sqrt(rowsum(A_hat)))
__device__ float g_z[Bc * Nc * Oc];       // 8 MB:  z = (D x) W

// ---------------------------------------------------------------------------
// Kernel 1: row sums of A_hat -> d.  One warp per row.
// rowsum(A_hat)[n] = sum_m A[n,m] - A[n,n] + 1
// ---------------------------------------------------------------------------
__global__ __launch_bounds__(256) void k_rowsum(const float* __restrict__ adj) {
    int warps_per_block = blockDim.x >> 5;
    int row = blockIdx.x * warps_per_block + (threadIdx.x >> 5);
    if (row >= Bc * Nc) return;
    int lane = threadIdx.x & 31;
    const float4* a = reinterpret_cast<const float4*>(adj + (size_t)row * Nc);
    float s = 0.f;
#pragma unroll 4
    for (int i = lane; i < Nc / 4; i += 32) {
        float4 v = __ldg(a + i);
        s += (v.x + v.y) + (v.z + v.w);
    }
#pragma unroll
    for (int off = 16; off; off >>= 1) s += __shfl_xor_sync(0xffffffffu, s, off);
    if (lane == 0) {
        int n = row & (Nc - 1);
        float diag = __ldg(adj + (size_t)row * Nc + n);
        float rs = s - diag + 1.0f;
        g_d[row] = 1.0f / (1e-6f + sqrtf(rs));
    }
}

// ---------------------------------------------------------------------------
// Kernel 2: z[r, o] = d[r] * sum_f x[r, f] * W[f, o]   (r = b*N+n, M=16384)
// Tiled SGEMM: BM=128, BN=128(=Oc), BK=8, 256 threads, 8x8 per-thread tile.
// ---------------------------------------------------------------------------
__global__ __launch_bounds__(256) void k_xw(const float* __restrict__ x,
                                            const float* __restrict__ W) {
    __shared__ float As[8][132];   // [k][m], padded -> conflict-free
    __shared__ float Bs[8][128];   // [k][o]
    int tid = threadIdx.x;
    int tx = tid & 15, ty = tid >> 4;
    int rowBase = blockIdx.x * 128;

    float c[8][8] = {};

    int aIdx = tid * 4;
    int aR = aIdx >> 3, aK = aIdx & 7;     // 8 floats per row per k-tile
    int bK = tid >> 5, bC = (tid & 31) * 4;

    for (int k0 = 0; k0 < Fc; k0 += 8) {
        float4 va = *reinterpret_cast<const float4*>(
            x + (size_t)(rowBase + aR) * Fc + k0 + aK);
        float4 vb = *reinterpret_cast<const float4*>(
            W + (size_t)(bK + k0) * Oc + bC);
        __syncthreads();
        As[aK + 0][aR] = va.x; As[aK + 1][aR] = va.y;
        As[aK + 2][aR] = va.z; As[aK + 3][aR] = va.w;
        *reinterpret_cast<float4*>(&Bs[bK][bC]) = vb;
        __syncthreads();
#pragma unroll
        for (int k = 0; k < 8; ++k) {
            float a[8], b[8];
#pragma unroll
            for (int i = 0; i < 8; i++) a[i] = As[k][ty * 8 + i];
#pragma unroll
            for (int j = 0; j < 8; j++) b[j] = Bs[k][tx * 8 + j];
#pragma unroll
            for (int i = 0; i < 8; i++)
#pragma unroll
                for (int j = 0; j < 8; j++) c[i][j] += a[i] * b[j];
        }
    }
    // epilogue: scale row r by d[r]
#pragma unroll
    for (int i = 0; i < 8; i++) {
        int row = rowBase + ty * 8 + i;
        float dv = g_d[row];
#pragma unroll
        for (int j = 0; j < 8; j += 4) {
            float4 v;
            v.x = dv * c[i][j + 0];
            v.y = dv * c[i][j + 1];
            v.z = dv * c[i][j + 2];
            v.w = dv * c[i][j + 3];
            *reinterpret_cast<float4*>(g_z + (size_t)row * Oc + tx * 8 + j) = v;
        }
    }
}

// ---------------------------------------------------------------------------
// Kernel 3: out[b,n,o] = relu( d[n] * ( sum_m A[b,n,m] z[b,m,o]
//                                       + (1 - A[b,n,n]) z[b,n,o] ) )
// Tiled SGEMM per batch: M=2048, N=128(=Oc), K=2048. BM=128, BK=8.
// Grid: (16 m-tiles, 8 batches) = 128 blocks (~one wave).
// ---------------------------------------------------------------------------
__global__ __launch_bounds__(256) void k_main(const float* __restrict__ adj,
                                              float* __restrict__ out) {
    __shared__ float As[8][132];
    __shared__ float Bs[8][128];
    int tid = threadIdx.x;
    int tx = tid & 15, ty = tid >> 4;
    int b = blockIdx.y;
    int rowBase = blockIdx.x * 128;

    const float* A = adj + (size_t)b * Nc * Nc;
    const float* Z = g_z + (size_t)b * Nc * Oc;

    float c[8][8] = {};

    int aIdx = tid * 4;
    int aR = aIdx >> 3, aK = aIdx & 7;
    int bK = tid >> 5, bC = (tid & 31) * 4;

    for (int k0 = 0; k0 < Nc; k0 += 8) {
        float4 va = *reinterpret_cast<const float4*>(
            A + (size_t)(rowBase + aR) * Nc + k0 + aK);
        float4 vb = *reinterpret_cast<const float4*>(
            Z + (size_t)(bK + k0) * Oc + bC);
        __syncthreads();
        As[aK + 0][aR] = va.x; As[aK + 1][aR] = va.y;
        As[aK + 2][aR] = va.z; As[aK + 3][aR] = va.w;
        *reinterpret_cast<float4*>(&Bs[bK][bC]) = vb;
        __syncthreads();
#pragma unroll
        for (int k = 0; k < 8; ++k) {
            float a[8], bb[8];
#pragma unroll
            for (int i = 0; i < 8; i++) a[i] = As[k][ty * 8 + i];
#pragma unroll
            for (int j = 0; j < 8; j++) bb[j] = Bs[k][tx * 8 + j];
#pragma unroll
            for (int i = 0; i < 8; i++)
#pragma unroll
                for (int j = 0; j < 8; j++) c[i][j] += a[i] * bb[j];
        }
    }

    // Epilogue: diagonal correction + d[n] scale + relu
#pragma unroll
    for (int i = 0; i < 8; i++) {
        int n = rowBase + ty * 8 + i;
        float diag = __ldg(A + (size_t)n * Nc + n);
        float corr = 1.0f - diag;
        float dv = g_d[b * Nc + n];
        const float4* zrow = reinterpret_cast<const float4*>(Z + (size_t)n * Oc);
#pragma unroll
        for (int j = 0; j < 8; j += 4) {
            float4 zv = __ldg(zrow + (tx * 8 + j) / 4);
            float4 v;
            v.x = fmaxf(dv * (c[i][j + 0] + corr * zv.x), 0.f);
            v.y = fmaxf(dv * (c[i][j + 1] + corr * zv.y), 0.f);
            v.z = fmaxf(dv * (c[i][j + 2] + corr * zv.z), 0.f);
            v.w = fmaxf(dv * (c[i][j + 3] + corr * zv.w), 0.f);
            *reinterpret_cast<float4*>(
                out + ((size_t)b * Nc + n) * Oc + tx * 8 + j) = v;
        }
    }
}

// ---------------------------------------------------------------------------
extern "C" void kernel_launch(void* const* d_in, const int* in_sizes, int n_in,
                              void* d_out, int out_size) {
    const float* x   = (const float*)d_in[0];   // [8,2048,128]
    const float* adj = (const float*)d_in[1];   // [8,2048,2048]
    const float* W   = (const float*)d_in[2];   // [128,128]
    float* out = (float*)d_out;                 // [8,2048,128]

    k_rowsum<<<(Bc * Nc) / 8, 256>>>(adj);          // 8 warps/block, warp/row
    k_xw<<<(Bc * Nc) / 128, 256>>>(x, W);           // 128 blocks
    k_main<<<dim3(Nc / 128, Bc), 256>>>(adj, out);  // 128 blocks
}

// round 4
// speedup vs baseline: 1.0075x; 1.0075x over previous
#include <cuda_runtime.h>
#include <math.h>

// Problem shape (fixed by setup_inputs)
constexpr int Bc = 8;     // batch
constexpr int Nc = 2048;  // nodes
constexpr int Fc = 128;   // in features
constexpr int Oc = 128;   // out features

// Scratch (static __device__ — allocation-free per harness rules)
__device__ float g_d[Bc * Nc];            // 64 KB: 1/(eps+sqrt(rowsum(A_hat)))
__device__ float g_z[Bc * Nc * Oc];       // 8 MB:  z = (D x) W

// ---------------------------------------------------------------------------
// Kernel 1: row sums of A_hat -> d.  One warp per row.
// rowsum(A_hat)[n] = sum_m A[n,m] - A[n,n] + 1
// ---------------------------------------------------------------------------
__global__ __launch_bounds__(256) void k_rowsum(const float* __restrict__ adj) {
    int warps_per_block = blockDim.x >> 5;
    int row = blockIdx.x * warps_per_block + (threadIdx.x >> 5);
    if (row >= Bc * Nc) return;
    int lane = threadIdx.x & 31;
    const float4* a = reinterpret_cast<const float4*>(adj + (size_t)row * Nc);
    float s = 0.f;
#pragma unroll 4
    for (int i = lane; i < Nc / 4; i += 32) {
        float4 v = __ldg(a + i);
        s += (v.x + v.y) + (v.z + v.w);
    }
#pragma unroll
    for (int off = 16; off; off >>= 1) s += __shfl_xor_sync(0xffffffffu, s, off);
    if (lane == 0) {
        int n = row & (Nc - 1);
        float diag = __ldg(adj + (size_t)row * Nc + n);
        float rs = s - diag + 1.0f;
        g_d[row] = 1.0f / (1e-6f + sqrtf(rs));
    }
}

// ---------------------------------------------------------------------------
// Kernel 2: z[r, o] = d[r] * sum_f x[r, f] * W[f, o]   (r = b*N+n, M=16384)
// Tiled SGEMM: BM=128, BN=128(=Oc), BK=8, 256 threads, 8x8 per-thread tile.
// ---------------------------------------------------------------------------
__global__ __launch_bounds__(256) void k_xw(const float* __restrict__ x,
                                            const float* __restrict__ W) {
    __shared__ float As[8][132];   // [k][m], padded -> conflict-free
    __shared__ float Bs[8][128];   // [k][o]
    int tid = threadIdx.x;
    int tx = tid & 15, ty = tid >> 4;
    int rowBase = blockIdx.x * 128;

    float c[8][8] = {};

    int aIdx = tid * 4;
    int aR = aIdx >> 3, aK = aIdx & 7;     // 8 floats per row per k-tile
    int bK = tid >> 5, bC = (tid & 31) * 4;

    for (int k0 = 0; k0 < Fc; k0 += 8) {
        float4 va = *reinterpret_cast<const float4*>(
            x + (size_t)(rowBase + aR) * Fc + k0 + aK);
        float4 vb = *reinterpret_cast<const float4*>(
            W + (size_t)(bK + k0) * Oc + bC);
        __syncthreads();
        As[aK + 0][aR] = va.x; As[aK + 1][aR] = va.y;
        As[aK + 2][aR] = va.z; As[aK + 3][aR] = va.w;
        *reinterpret_cast<float4*>(&Bs[bK][bC]) = vb;
        __syncthreads();
#pragma unroll
        for (int k = 0; k < 8; ++k) {
            float a[8], b[8];
#pragma unroll
            for (int i = 0; i < 8; i++) a[i] = As[k][ty * 8 + i];
#pragma unroll
            for (int j = 0; j < 8; j++) b[j] = Bs[k][tx * 8 + j];
#pragma unroll
            for (int i = 0; i < 8; i++)
#pragma unroll
                for (int j = 0; j < 8; j++) c[i][j] += a[i] * b[j];
        }
    }
    // epilogue: scale row r by d[r]
#pragma unroll
    for (int i = 0; i < 8; i++) {
        int row = rowBase + ty * 8 + i;
        float dv = g_d[row];
#pragma unroll
        for (int j = 0; j < 8; j += 4) {
            float4 v;
            v.x = dv * c[i][j + 0];
            v.y = dv * c[i][j + 1];
            v.z = dv * c[i][j + 2];
            v.w = dv * c[i][j + 3];
            *reinterpret_cast<float4*>(g_z + (size_t)row * Oc + tx * 8 + j) = v;
        }
    }
}

// ---------------------------------------------------------------------------
// Kernel 3: out[b,n,o] = relu( d[n] * ( sum_m A[b,n,m] z[b,m,o]
//                                       + (1 - A[b,n,n]) z[b,n,o] ) )
// Tiled SGEMM per batch: M=2048, N=128(=Oc), K=2048. BM=128, BK=8.
// Grid: (16 m-tiles, 8 batches) = 128 blocks (~one wave).
// ---------------------------------------------------------------------------
__global__ __launch_bounds__(256) void k_main(const float* __restrict__ adj,
                                              float* __restrict__ out) {
    __shared__ float As[8][132];
    __shared__ float Bs[8][128];
    int tid = threadIdx.x;
    int tx = tid & 15, ty = tid >> 4;
    int b = blockIdx.y;
    int rowBase = blockIdx.x * 128;

    const float* A = adj + (size_t)b * Nc * Nc;
    const float* Z = g_z + (size_t)b * Nc * Oc;

    float c[8][8] = {};

    int aIdx = tid * 4;
    int aR = aIdx >> 3, aK = aIdx & 7;
    int bK = tid >> 5, bC = (tid & 31) * 4;

    for (int k0 = 0; k0 < Nc; k0 += 8) {
        float4 va = *reinterpret_cast<const float4*>(
            A + (size_t)(rowBase + aR) * Nc + k0 + aK);
        float4 vb = *reinterpret_cast<const float4*>(
            Z + (size_t)(bK + k0) * Oc + bC);
        __syncthreads();
        As[aK + 0][aR] = va.x; As[aK + 1][aR] = va.y;
        As[aK + 2][aR] = va.z; As[aK + 3][aR] = va.w;
        *reinterpret_cast<float4*>(&Bs[bK][bC]) = vb;
        __syncthreads();
#pragma unroll
        for (int k = 0; k < 8; ++k) {
            float a[8], bb[8];
#pragma unroll
            for (int i = 0; i < 8; i++) a[i] = As[k][ty * 8 + i];
#pragma unroll
            for (int j = 0; j < 8; j++) bb[j] = Bs[k][tx * 8 + j];
#pragma unroll
            for (int i = 0; i < 8; i++)
#pragma unroll
                for (int j = 0; j < 8; j++) c[i][j] += a[i] * bb[j];
        }
    }

    // Epilogue: diagonal correction + d[n] scale + relu
#pragma unroll
    for (int i = 0; i < 8; i++) {
        int n = rowBase + ty * 8 + i;
        float diag = __ldg(A + (size_t)n * Nc + n);
        float corr = 1.0f - diag;
        float dv = g_d[b * Nc + n];
        const float4* zrow = reinterpret_cast<const float4*>(Z + (size_t)n * Oc);
#pragma unroll
        for (int j = 0; j < 8; j += 4) {
            float4 zv = __ldg(zrow + (tx * 8 + j) / 4);
            float4 v;
            v.x = fmaxf(dv * (c[i][j + 0] + corr * zv.x), 0.f);
            v.y = fmaxf(dv * (c[i][j + 1] + corr * zv.y), 0.f);
            v.z = fmaxf(dv * (c[i][j + 2] + corr * zv.z), 0.f);
            v.w = fmaxf(dv * (c[i][j + 3] + corr * zv.w), 0.f);
            *reinterpret_cast<float4*>(
                out + ((size_t)b * Nc + n) * Oc + tx * 8 + j) = v;
        }
    }
}

// ---------------------------------------------------------------------------
extern "C" void kernel_launch(void* const* d_in, const int* in_sizes, int n_in,
                              void* d_out, int out_size) {
    const float* x   = (const float*)d_in[0];   // [8,2048,128]
    const float* adj = (const float*)d_in[1];   // [8,2048,2048]
    const float* W   = (const float*)d_in[2];   // [128,128]
    float* out = (float*)d_out;                 // [8,2048,128]

    k_rowsum<<<(Bc * Nc) / 8, 256>>>(adj);          // 8 warps/block, warp/row
    k_xw<<<(Bc * Nc) / 128, 256>>>(x, W);           // 128 blocks
    k_main<<<dim3(Nc / 128, Bc), 256>>>(adj, out);  // 128 blocks
}

// round 9
// speedup vs baseline: 2.9733x; 2.9511x over previous
#include <cuda_runtime.h>
#include <math.h>
#include <stdint.h>

// Problem shape (fixed by setup_inputs)
constexpr int Bc = 8;     // batch
constexpr int Nc = 2048;  // nodes
constexpr int Fc = 128;   // in features
constexpr int Oc = 128;   // out features

// Scratch (static __device__ — allocation-free per harness rules)
__device__ float g_d[Bc * Nc];            // 1/(eps+sqrt(rowsum(A_hat)))
__device__ float g_z[Bc * Nc * Oc];       // z[m,o]  = d[m] * (x W)[m,o]   (row-major)
__device__ float g_zT[Bc * Oc * Nc];      // zT[o,m] = same, transposed (n-major B operand)

// ---------------------------------------------------------------------------
// Generic-PTX helpers (sm_80+ features only: cp.async, ldmatrix, mma.sync tf32)
// ---------------------------------------------------------------------------
__device__ __forceinline__ uint32_t smem_u32(const void* p) {
    uint32_t a;
    asm("{ .reg .u64 t; cvta.to.shared.u64 t, %1; cvt.u32.u64 %0, t; }"
        : "=r"(a) : "l"(p));
    return a;
}
__device__ __forceinline__ void cp16(uint32_t s, const void* g) {
    asm volatile("cp.async.cg.shared.global [%0], [%1], 16;\n" :: "r"(s), "l"(g));
}
#define CP_COMMIT()  asm volatile("cp.async.commit_group;\n" ::: "memory")
#define CP_WAIT(N)   asm volatile("cp.async.wait_group " #N ";\n" ::: "memory")

// ldmatrix x4 over four 8-row x 16B sub-tiles (raw 32-bit payload is fine)
#define LDSM4(r, addr) \
    asm volatile("ldmatrix.sync.aligned.m8n8.x4.shared.b16 {%0,%1,%2,%3}, [%4];" \
                 : "=r"((r)[0]), "=r"((r)[1]), "=r"((r)[2]), "=r"((r)[3]) \
                 : "r"(addr))

// round-to-nearest tf32 (halves truncation error vs raw HMMA truncate)
#define TO_TF32(x) asm volatile("cvt.rna.tf32.f32 %0, %0;" : "+r"(x))

#define MMA_TF32(c, a, bb) \
    asm volatile( \
        "mma.sync.aligned.m16n8k8.row.col.f32.tf32.tf32.f32 " \
        "{%0,%1,%2,%3}, {%4,%5,%6,%7}, {%8,%9}, {%0,%1,%2,%3};" \
        : "+f"((c)[0]), "+f"((c)[1]), "+f"((c)[2]), "+f"((c)[3]) \
        : "r"((a)[0]), "r"((a)[1]), "r"((a)[2]), "r"((a)[3]), \
          "r"((bb)[0]), "r"((bb)[1]))

// ---------------------------------------------------------------------------
// Kernel 1: row sums of A_hat -> d.  One warp per row. (HBM-bound, 74% DRAM)
// ---------------------------------------------------------------------------
__global__ __launch_bounds__(256) void k_rowsum(const float* __restrict__ adj) {
    int warps_per_block = blockDim.x >> 5;
    int row = blockIdx.x * warps_per_block + (threadIdx.x >> 5);
    if (row >= Bc * Nc) return;
    int lane = threadIdx.x & 31;
    const float4* a = reinterpret_cast<const float4*>(adj + (size_t)row * Nc);
    float s = 0.f;
#pragma unroll 4
    for (int i = lane; i < Nc / 4; i += 32) {
        float4 v = __ldg(a + i);
        s += (v.x + v.y) + (v.z + v.w);
    }
#pragma unroll
    for (int off = 16; off; off >>= 1) s += __shfl_xor_sync(0xffffffffu, s, off);
    if (lane == 0) {
        int n = row & (Nc - 1);
        float diag = __ldg(adj + (size_t)row * Nc + n);
        float rs = s - diag + 1.0f;
        g_d[row] = 1.0f / (1e-6f + sqrtf(rs));
    }
}

// ---------------------------------------------------------------------------
// Kernel 2: z[r,o] = d[r] * sum_f x[r,f] W[f,o]; writes row-major AND transposed.
// Exact fp32 so tf32 error enters only once (in k_main).
// ---------------------------------------------------------------------------
__global__ __launch_bounds__(256) void k_xw(const float* __restrict__ x,
                                            const float* __restrict__ W) {
    __shared__ float As[8][132];
    __shared__ float Bs[8][128];
    int tid = threadIdx.x;
    int tx = tid & 15, ty = tid >> 4;
    int rowBase = blockIdx.x * 128;

    float c[8][8] = {};

    int aIdx = tid * 4;
    int aR = aIdx >> 3, aK = aIdx & 7;
    int bK = tid >> 5, bC = (tid & 31) * 4;

    for (int k0 = 0; k0 < Fc; k0 += 8) {
        float4 va = *reinterpret_cast<const float4*>(
            x + (size_t)(rowBase + aR) * Fc + k0 + aK);
        float4 vb = *reinterpret_cast<const float4*>(
            W + (size_t)(bK + k0) * Oc + bC);
        __syncthreads();
        As[aK + 0][aR] = va.x; As[aK + 1][aR] = va.y;
        As[aK + 2][aR] = va.z; As[aK + 3][aR] = va.w;
        *reinterpret_cast<float4*>(&Bs[bK][bC]) = vb;
        __syncthreads();
#pragma unroll
        for (int k = 0; k < 8; ++k) {
            float a[8], b[8];
#pragma unroll
            for (int i = 0; i < 8; i++) a[i] = As[k][ty * 8 + i];
#pragma unroll
            for (int j = 0; j < 8; j++) b[j] = Bs[k][tx * 8 + j];
#pragma unroll
            for (int i = 0; i < 8; i++)
#pragma unroll
                for (int j = 0; j < 8; j++) c[i][j] += a[i] * b[j];
        }
    }

    float dvv[8];
#pragma unroll
    for (int i = 0; i < 8; i++) dvv[i] = g_d[rowBase + ty * 8 + i];

    // row-major z
#pragma unroll
    for (int i = 0; i < 8; i++) {
        int row = rowBase + ty * 8 + i;
#pragma unroll
        for (int j = 0; j < 8; j += 4) {
            float4 v;
            v.x = dvv[i] * c[i][j + 0];
            v.y = dvv[i] * c[i][j + 1];
            v.z = dvv[i] * c[i][j + 2];
            v.w = dvv[i] * c[i][j + 3];
            *reinterpret_cast<float4*>(g_z + (size_t)row * Oc + tx * 8 + j) = v;
        }
    }
    // transposed zT[b][o][m]
    int bb = rowBase >> 11;
    int mbase = (rowBase & (Nc - 1)) + ty * 8;
#pragma unroll
    for (int j = 0; j < 8; j++) {
        int o = tx * 8 + j;
        float* dst = g_zT + ((size_t)bb * Oc + o) * Nc + mbase;
        float4 v0, v1;
        v0.x = dvv[0] * c[0][j]; v0.y = dvv[1] * c[1][j];
        v0.z = dvv[2] * c[2][j]; v0.w = dvv[3] * c[3][j];
        v1.x = dvv[4] * c[4][j]; v1.y = dvv[5] * c[5][j];
        v1.z = dvv[6] * c[6][j]; v1.w = dvv[7] * c[7][j];
        *reinterpret_cast<float4*>(dst)     = v0;
        *reinterpret_cast<float4*>(dst + 4) = v1;
    }
}

// ---------------------------------------------------------------------------
// Kernel 3: tf32 mma.sync GEMM (generic PTX — compiles for compute_103).
// out[b,n,o] = relu( d[n] * ( sum_m A[b,n,m] z[b,m,o] + (1-A[b,n,n]) z[b,n,o] ) )
// BM=128, BN=128, BK=32, 4-stage cp.async pipeline (128 KB smem).
// 8 warps: warpM = wid&1 (2 x 64 rows), warpN = wid>>1 (4 x 32 cols).
// Per warp: 4x4 grid of m16n8k8 tiles. Fragments via ldmatrix from
// XOR-swizzled K-major tiles (A = adj rows; B = zT rows, both k-contiguous).
// ---------------------------------------------------------------------------
constexpr int BK      = 32;
constexpr int K_ITERS = Nc / BK;              // 64
constexpr int TILE_B  = 128 * BK * 4;         // 16384 per operand
constexpr int STAGE_B = 2 * TILE_B;           // 32768 (A + B)
constexpr int SMEM_SZ = 4 * STAGE_B;          // 131072

// swizzled 16B-chunk offset within a [128 rows x 32 floats] tile
__device__ __forceinline__ uint32_t sw(int r, int ch) {   // ch in 0..7 (16B units)
    return (uint32_t)(r * 128) + (uint32_t)(((ch ^ (r & 7)) << 4));
}
// ldmatrix.x4 source address for lane: 4 sub-tiles (rows +0/+8, chunks +0/+1)
__device__ __forceinline__ uint32_t ldsm_addr(uint32_t base, int rowBase,
                                              int chunkBase, int lane) {
    int row = rowBase + (lane & 7) + (((lane >> 3) & 1) << 3);
    int ch  = chunkBase + (lane >> 4);
    return base + sw(row, ch);
}

__global__ __launch_bounds__(256, 1) void k_main_mma(const float* __restrict__ adj,
                                                     float* __restrict__ out) {
    extern __shared__ __align__(1024) char smem[];
    uint32_t sb = smem_u32(smem);
    int tid = threadIdx.x, wid = tid >> 5, lane = tid & 31;
    int b = blockIdx.y, rowBase = blockIdx.x * 128;
    int warpM = wid & 1, warpN = wid >> 1;

    const float* A  = adj  + (size_t)b * Nc * Nc;
    const float* ZT = g_zT + (size_t)b * Oc * Nc;

    float c[4][4][4] = {};

    auto issue = [&](int it) {
        int s = it & 3;
        uint32_t baseA = sb + s * STAGE_B;
        uint32_t baseB = baseA + TILE_B;
        int k0 = it * BK;
#pragma unroll
        for (int t = 0; t < 4; t++) {          // 1024 chunks per operand / 256 thr
            int idx = tid + t * 256;
            int r = idx >> 3, ch = idx & 7;
            uint32_t so = sw(r, ch);
            cp16(baseA + so, A  + (size_t)(rowBase + r) * Nc + k0 + ch * 4);
            cp16(baseB + so, ZT + (size_t)r * Nc + k0 + ch * 4);
        }
        CP_COMMIT();
    };

    issue(0); issue(1); issue(2);

    for (int it = 0; it < K_ITERS; ++it) {
        if (it + 3 < K_ITERS) { issue(it + 3); CP_WAIT(3); }
        else                  { CP_WAIT(0); }
        __syncthreads();

        int s = it & 3;
        uint32_t baseA = sb + s * STAGE_B;
        uint32_t baseB = baseA + TILE_B;
#pragma unroll
        for (int ks = 0; ks < 4; ++ks) {       // four k8 steps within BK=32
            uint32_t a[4][4];
#pragma unroll
            for (int mt = 0; mt < 4; ++mt) {
                uint32_t ad = ldsm_addr(baseA, warpM * 64 + mt * 16, ks * 2, lane);
                LDSM4(a[mt], ad);
#pragma unroll
                for (int q = 0; q < 4; q++) TO_TF32(a[mt][q]);
            }
            uint32_t bf[4][2];
#pragma unroll
            for (int p = 0; p < 2; ++p) {      // two n16 groups -> four n8 tiles
                uint32_t r4[4];
                uint32_t ad = ldsm_addr(baseB, warpN * 32 + p * 16, ks * 2, lane);
                LDSM4(r4, ad);
#pragma unroll
                for (int q = 0; q < 4; q++) TO_TF32(r4[q]);
                bf[2 * p + 0][0] = r4[0]; bf[2 * p + 0][1] = r4[2];
                bf[2 * p + 1][0] = r4[1]; bf[2 * p + 1][1] = r4[3];
            }
#pragma unroll
            for (int mt = 0; mt < 4; ++mt)
#pragma unroll
                for (int nt = 0; nt < 4; ++nt)
                    MMA_TF32(c[mt][nt], a[mt], bf[nt]);
        }
        __syncthreads();
    }

    // Epilogue: diagonal correction + d[n] scale + relu, from C fragments.
    // c0,c1 -> (row = lane/4, cols 2*(lane%4)+{0,1}); c2,c3 -> row+8.
    int gr = lane >> 2, tg = lane & 3;
#pragma unroll
    for (int mt = 0; mt < 4; ++mt) {
        int n0 = rowBase + warpM * 64 + mt * 16 + gr;
        int n1 = n0 + 8;
        size_t rg0 = (size_t)b * Nc + n0;
        size_t rg1 = (size_t)b * Nc + n1;
        float corr0 = 1.0f - __ldg(A + (size_t)n0 * Nc + n0);
        float corr1 = 1.0f - __ldg(A + (size_t)n1 * Nc + n1);
        float dv0 = g_d[rg0], dv1 = g_d[rg1];
#pragma unroll
        for (int nt = 0; nt < 4; ++nt) {
            int o = warpN * 32 + nt * 8 + 2 * tg;
            float2 z0 = *reinterpret_cast<const float2*>(g_z + rg0 * Oc + o);
            float2 z1 = *reinterpret_cast<const float2*>(g_z + rg1 * Oc + o);
            float2 v0, v1;
            v0.x = fmaxf(dv0 * (c[mt][nt][0] + corr0 * z0.x), 0.f);
            v0.y = fmaxf(dv0 * (c[mt][nt][1] + corr0 * z0.y), 0.f);
            v1.x = fmaxf(dv1 * (c[mt][nt][2] + corr1 * z1.x), 0.f);
            v1.y = fmaxf(dv1 * (c[mt][nt][3] + corr1 * z1.y), 0.f);
            *reinterpret_cast<float2*>(out + rg0 * Oc + o) = v0;
            *reinterpret_cast<float2*>(out + rg1 * Oc + o) = v1;
        }
    }
}

// ---------------------------------------------------------------------------
extern "C" void kernel_launch(void* const* d_in, const int* in_sizes, int n_in,
                              void* d_out, int out_size) {
    const float* x   = (const float*)d_in[0];   // [8,2048,128]
    const float* adj = (const float*)d_in[1];   // [8,2048,2048]
    const float* W   = (const float*)d_in[2];   // [128,128]
    float* out = (float*)d_out;                 // [8,2048,128]

    cudaFuncSetAttribute(k_main_mma, cudaFuncAttributeMaxDynamicSharedMemorySize,
                         SMEM_SZ);

    k_rowsum<<<(Bc * Nc) / 8, 256>>>(adj);
    k_xw<<<(Bc * Nc) / 128, 256>>>(x, W);
    k_main_mma<<<dim3(Nc / 128, Bc), 256, SMEM_SZ>>>(adj, out);
}

// round 10
// speedup vs baseline: 2.9841x; 1.0036x over previous
#include <cuda_runtime.h>
#include <math.h>
#include <stdint.h>

// Problem shape (fixed by setup_inputs)
constexpr int Bc = 8;     // batch
constexpr int Nc = 2048;  // nodes
constexpr int Fc = 128;   // in features
constexpr int Oc = 128;   // out features

// Scratch (static __device__ — allocation-free per harness rules)
__device__ float g_d[Bc * Nc];            // 1/(eps+sqrt(rowsum(A_hat)))
__device__ float g_z[Bc * Nc * Oc];       // z[m,o]  = d[m] * (x W)[m,o]   (row-major)
__device__ float g_zT[Bc * Oc * Nc];      // zT[o,m] = same, transposed (n-major B operand)

// ---------------------------------------------------------------------------
// Generic-PTX helpers (sm_80+ features only: cp.async, ldmatrix, mma.sync tf32)
// ---------------------------------------------------------------------------
__device__ __forceinline__ uint32_t smem_u32(const void* p) {
    uint32_t a;
    asm("{ .reg .u64 t; cvta.to.shared.u64 t, %1; cvt.u32.u64 %0, t; }"
        : "=r"(a) : "l"(p));
    return a;
}
__device__ __forceinline__ void cp16(uint32_t s, const void* g) {
    asm volatile("cp.async.cg.shared.global [%0], [%1], 16;\n" :: "r"(s), "l"(g));
}
#define CP_COMMIT()  asm volatile("cp.async.commit_group;\n" ::: "memory")
#define CP_WAIT(N)   asm volatile("cp.async.wait_group " #N ";\n" ::: "memory")

// ldmatrix x4 over four 8-row x 16B sub-tiles (raw 32-bit payload is fine)
#define LDSM4(r, addr) \
    asm volatile("ldmatrix.sync.aligned.m8n8.x4.shared.b16 {%0,%1,%2,%3}, [%4];" \
                 : "=r"((r)[0]), "=r"((r)[1]), "=r"((r)[2]), "=r"((r)[3]) \
                 : "r"(addr))

// round-to-nearest tf32 (halves truncation error vs raw HMMA truncate)
#define TO_TF32(x) asm volatile("cvt.rna.tf32.f32 %0, %0;" : "+r"(x))

#define MMA_TF32(c, a, bb) \
    asm volatile( \
        "mma.sync.aligned.m16n8k8.row.col.f32.tf32.tf32.f32 " \
        "{%0,%1,%2,%3}, {%4,%5,%6,%7}, {%8,%9}, {%0,%1,%2,%3};" \
        : "+f"((c)[0]), "+f"((c)[1]), "+f"((c)[2]), "+f"((c)[3]) \
        : "r"((a)[0]), "r"((a)[1]), "r"((a)[2]), "r"((a)[3]), \
          "r"((bb)[0]), "r"((bb)[1]))

// ---------------------------------------------------------------------------
// Kernel 1: row sums of A_hat -> d.  One warp per row. (HBM-bound, 74% DRAM)
// ---------------------------------------------------------------------------
__global__ __launch_bounds__(256) void k_rowsum(const float* __restrict__ adj) {
    int warps_per_block = blockDim.x >> 5;
    int row = blockIdx.x * warps_per_block + (threadIdx.x >> 5);
    if (row >= Bc * Nc) return;
    int lane = threadIdx.x & 31;
    const float4* a = reinterpret_cast<const float4*>(adj + (size_t)row * Nc);
    float s = 0.f;
#pragma unroll 4
    for (int i = lane; i < Nc / 4; i += 32) {
        float4 v = __ldg(a + i);
        s += (v.x + v.y) + (v.z + v.w);
    }
#pragma unroll
    for (int off = 16; off; off >>= 1) s += __shfl_xor_sync(0xffffffffu, s, off);
    if (lane == 0) {
        int n = row & (Nc - 1);
        float diag = __ldg(adj + (size_t)row * Nc + n);
        float rs = s - diag + 1.0f;
        g_d[row] = 1.0f / (1e-6f + sqrtf(rs));
    }
}

// ---------------------------------------------------------------------------
// Kernel 2: z[r,o] = d[r] * sum_f x[r,f] W[f,o]; writes row-major AND transposed.
// Exact fp32 so tf32 error enters only once (in k_main).
// ---------------------------------------------------------------------------
__global__ __launch_bounds__(256) void k_xw(const float* __restrict__ x,
                                            const float* __restrict__ W) {
    __shared__ float As[8][132];
    __shared__ float Bs[8][128];
    int tid = threadIdx.x;
    int tx = tid & 15, ty = tid >> 4;
    int rowBase = blockIdx.x * 128;

    float c[8][8] = {};

    int aIdx = tid * 4;
    int aR = aIdx >> 3, aK = aIdx & 7;
    int bK = tid >> 5, bC = (tid & 31) * 4;

    for (int k0 = 0; k0 < Fc; k0 += 8) {
        float4 va = *reinterpret_cast<const float4*>(
            x + (size_t)(rowBase + aR) * Fc + k0 + aK);
        float4 vb = *reinterpret_cast<const float4*>(
            W + (size_t)(bK + k0) * Oc + bC);
        __syncthreads();
        As[aK + 0][aR] = va.x; As[aK + 1][aR] = va.y;
        As[aK + 2][aR] = va.z; As[aK + 3][aR] = va.w;
        *reinterpret_cast<float4*>(&Bs[bK][bC]) = vb;
        __syncthreads();
#pragma unroll
        for (int k = 0; k < 8; ++k) {
            float a[8], b[8];
#pragma unroll
            for (int i = 0; i < 8; i++) a[i] = As[k][ty * 8 + i];
#pragma unroll
            for (int j = 0; j < 8; j++) b[j] = Bs[k][tx * 8 + j];
#pragma unroll
            for (int i = 0; i < 8; i++)
#pragma unroll
                for (int j = 0; j < 8; j++) c[i][j] += a[i] * b[j];
        }
    }

    float dvv[8];
#pragma unroll
    for (int i = 0; i < 8; i++) dvv[i] = g_d[rowBase + ty * 8 + i];

    // row-major z
#pragma unroll
    for (int i = 0; i < 8; i++) {
        int row = rowBase + ty * 8 + i;
#pragma unroll
        for (int j = 0; j < 8; j += 4) {
            float4 v;
            v.x = dvv[i] * c[i][j + 0];
            v.y = dvv[i] * c[i][j + 1];
            v.z = dvv[i] * c[i][j + 2];
            v.w = dvv[i] * c[i][j + 3];
            *reinterpret_cast<float4*>(g_z + (size_t)row * Oc + tx * 8 + j) = v;
        }
    }
    // transposed zT[b][o][m]
    int bb = rowBase >> 11;
    int mbase = (rowBase & (Nc - 1)) + ty * 8;
#pragma unroll
    for (int j = 0; j < 8; j++) {
        int o = tx * 8 + j;
        float* dst = g_zT + ((size_t)bb * Oc + o) * Nc + mbase;
        float4 v0, v1;
        v0.x = dvv[0] * c[0][j]; v0.y = dvv[1] * c[1][j];
        v0.z = dvv[2] * c[2][j]; v0.w = dvv[3] * c[3][j];
        v1.x = dvv[4] * c[4][j]; v1.y = dvv[5] * c[5][j];
        v1.z = dvv[6] * c[6][j]; v1.w = dvv[7] * c[7][j];
        *reinterpret_cast<float4*>(dst)     = v0;
        *reinterpret_cast<float4*>(dst + 4) = v1;
    }
}

// ---------------------------------------------------------------------------
// Kernel 3: tf32 mma.sync GEMM (generic PTX — compiles for compute_103).
// out[b,n,o] = relu( d[n] * ( sum_m A[b,n,m] z[b,m,o] + (1-A[b,n,n]) z[b,n,o] ) )
// BM=128, BN=128, BK=32, 4-stage cp.async pipeline (128 KB smem).
// 8 warps: warpM = wid&1 (2 x 64 rows), warpN = wid>>1 (4 x 32 cols).
// Per warp: 4x4 grid of m16n8k8 tiles. Fragments via ldmatrix from
// XOR-swizzled K-major tiles (A = adj rows; B = zT rows, both k-contiguous).
// ---------------------------------------------------------------------------
constexpr int BK      = 32;
constexpr int K_ITERS = Nc / BK;              // 64
constexpr int TILE_B  = 128 * BK * 4;         // 16384 per operand
constexpr int STAGE_B = 2 * TILE_B;           // 32768 (A + B)
constexpr int SMEM_SZ = 4 * STAGE_B;          // 131072

// swizzled 16B-chunk offset within a [128 rows x 32 floats] tile
__device__ __forceinline__ uint32_t sw(int r, int ch) {   // ch in 0..7 (16B units)
    return (uint32_t)(r * 128) + (uint32_t)(((ch ^ (r & 7)) << 4));
}
// ldmatrix.x4 source address for lane: 4 sub-tiles (rows +0/+8, chunks +0/+1)
__device__ __forceinline__ uint32_t ldsm_addr(uint32_t base, int rowBase,
                                              int chunkBase, int lane) {
    int row = rowBase + (lane & 7) + (((lane >> 3) & 1) << 3);
    int ch  = chunkBase + (lane >> 4);
    return base + sw(row, ch);
}

__global__ __launch_bounds__(256, 1) void k_main_mma(const float* __restrict__ adj,
                                                     float* __restrict__ out) {
    extern __shared__ __align__(1024) char smem[];
    uint32_t sb = smem_u32(smem);
    int tid = threadIdx.x, wid = tid >> 5, lane = tid & 31;
    int b = blockIdx.y, rowBase = blockIdx.x * 128;
    int warpM = wid & 1, warpN = wid >> 1;

    const float* A  = adj  + (size_t)b * Nc * Nc;
    const float* ZT = g_zT + (size_t)b * Oc * Nc;

    float c[4][4][4] = {};

    auto issue = [&](int it) {
        int s = it & 3;
        uint32_t baseA = sb + s * STAGE_B;
        uint32_t baseB = baseA + TILE_B;
        int k0 = it * BK;
#pragma unroll
        for (int t = 0; t < 4; t++) {          // 1024 chunks per operand / 256 thr
            int idx = tid + t * 256;
            int r = idx >> 3, ch = idx & 7;
            uint32_t so = sw(r, ch);
            cp16(baseA + so, A  + (size_t)(rowBase + r) * Nc + k0 + ch * 4);
            cp16(baseB + so, ZT + (size_t)r * Nc + k0 + ch * 4);
        }
        CP_COMMIT();
    };

    issue(0); issue(1); issue(2);

    for (int it = 0; it < K_ITERS; ++it) {
        if (it + 3 < K_ITERS) { issue(it + 3); CP_WAIT(3); }
        else                  { CP_WAIT(0); }
        __syncthreads();

        int s = it & 3;
        uint32_t baseA = sb + s * STAGE_B;
        uint32_t baseB = baseA + TILE_B;
#pragma unroll
        for (int ks = 0; ks < 4; ++ks) {       // four k8 steps within BK=32
            uint32_t a[4][4];
#pragma unroll
            for (int mt = 0; mt < 4; ++mt) {
                uint32_t ad = ldsm_addr(baseA, warpM * 64 + mt * 16, ks * 2, lane);
                LDSM4(a[mt], ad);
#pragma unroll
                for (int q = 0; q < 4; q++) TO_TF32(a[mt][q]);
            }
            uint32_t bf[4][2];
#pragma unroll
            for (int p = 0; p < 2; ++p) {      // two n16 groups -> four n8 tiles
                uint32_t r4[4];
                uint32_t ad = ldsm_addr(baseB, warpN * 32 + p * 16, ks * 2, lane);
                LDSM4(r4, ad);
#pragma unroll
                for (int q = 0; q < 4; q++) TO_TF32(r4[q]);
                bf[2 * p + 0][0] = r4[0]; bf[2 * p + 0][1] = r4[2];
                bf[2 * p + 1][0] = r4[1]; bf[2 * p + 1][1] = r4[3];
            }
#pragma unroll
            for (int mt = 0; mt < 4; ++mt)
#pragma unroll
                for (int nt = 0; nt < 4; ++nt)
                    MMA_TF32(c[mt][nt], a[mt], bf[nt]);
        }
        __syncthreads();
    }

    // Epilogue: diagonal correction + d[n] scale + relu, from C fragments.
    // c0,c1 -> (row = lane/4, cols 2*(lane%4)+{0,1}); c2,c3 -> row+8.
    int gr = lane >> 2, tg = lane & 3;
#pragma unroll
    for (int mt = 0; mt < 4; ++mt) {
        int n0 = rowBase + warpM * 64 + mt * 16 + gr;
        int n1 = n0 + 8;
        size_t rg0 = (size_t)b * Nc + n0;
        size_t rg1 = (size_t)b * Nc + n1;
        float corr0 = 1.0f - __ldg(A + (size_t)n0 * Nc + n0);
        float corr1 = 1.0f - __ldg(A + (size_t)n1 * Nc + n1);
        float dv0 = g_d[rg0], dv1 = g_d[rg1];
#pragma unroll
        for (int nt = 0; nt < 4; ++nt) {
            int o = warpN * 32 + nt * 8 + 2 * tg;
            float2 z0 = *reinterpret_cast<const float2*>(g_z + rg0 * Oc + o);
            float2 z1 = *reinterpret_cast<const float2*>(g_z + rg1 * Oc + o);
            float2 v0, v1;
            v0.x = fmaxf(dv0 * (c[mt][nt][0] + corr0 * z0.x), 0.f);
            v0.y = fmaxf(dv0 * (c[mt][nt][1] + corr0 * z0.y), 0.f);
            v1.x = fmaxf(dv1 * (c[mt][nt][2] + corr1 * z1.x), 0.f);
            v1.y = fmaxf(dv1 * (c[mt][nt][3] + corr1 * z1.y), 0.f);
            *reinterpret_cast<float2*>(out + rg0 * Oc + o) = v0;
            *reinterpret_cast<float2*>(out + rg1 * Oc + o) = v1;
        }
    }
}

// ---------------------------------------------------------------------------
extern "C" void kernel_launch(void* const* d_in, const int* in_sizes, int n_in,
                              void* d_out, int out_size) {
    const float* x   = (const float*)d_in[0];   // [8,2048,128]
    const float* adj = (const float*)d_in[1];   // [8,2048,2048]
    const float* W   = (const float*)d_in[2];   // [128,128]
    float* out = (float*)d_out;                 // [8,2048,128]

    cudaFuncSetAttribute(k_main_mma, cudaFuncAttributeMaxDynamicSharedMemorySize,
                         SMEM_SZ);

    k_rowsum<<<(Bc * Nc) / 8, 256>>>(adj);
    k_xw<<<(Bc * Nc) / 128, 256>>>(x, W);
    k_main_mma<<<dim3(Nc / 128, Bc), 256, SMEM_SZ>>>(adj, out);
}